// round 15
// baseline (speedup 1.0000x reference)
#include <cuda_runtime.h>
#include <math.h>

#define BB 8
#define NN 2048
#define CC 32
#define DD 64
#define QQ 256
#define KK 205
#define JP 36           // padded j dimension (36 for 16B row alignment)
#define RANK (KK-1)
#define NT 288

typedef unsigned long long u64t;

// ---------------- scratch ----------------
__device__ float d_xl[BB*NN*CC];                  // 2 MB
__device__ __align__(16) float d_Wm1b[16384];     // Wm1 packed: [d/4][i][4]
__device__ __align__(16) float d_Wm2b[16384];     // Wm2 packed: [i/4][d][4]
// W2ext packed for j-partitioned epilogue (cross-lane variant, NO swaps)
__device__ __align__(16) float d_W2q[33*2048];

__device__ __forceinline__ float gelu_f(float x){
    return 0.5f*x*(1.0f+erff(x*0.70710678118654752440f));
}

__device__ __forceinline__ void cp_async16(float* smem_dst, const float4* gsrc){
    unsigned sm = (unsigned)__cvta_generic_to_shared(smem_dst);
    asm volatile("cp.async.cg.shared.global [%0], [%1], 16;\n" :: "r"(sm), "l"(gsrc));
}
#define CP_COMMIT() asm volatile("cp.async.commit_group;\n")
#define CP_WAIT(n)  asm volatile("cp.async.wait_group %0;\n" :: "n"(n))

// ---- packed fp32x2 helpers (Blackwell FFMA2) ----
__device__ __forceinline__ u64t pack_dup(float x){
    u64t r; unsigned u = __float_as_uint(x);
    asm("mov.b64 %0, {%1,%1};" : "=l"(r) : "r"(u));
    return r;
}
__device__ __forceinline__ void ffma2(u64t& d, u64t a, u64t b){
    asm("fma.rn.f32x2 %0, %1, %2, %0;" : "+l"(d) : "l"(a), "l"(b));
}
__device__ __forceinline__ float2 unpack2(u64t v){
    unsigned lo, hi;
    asm("mov.b64 {%0,%1}, %2;" : "=r"(lo), "=r"(hi) : "l"(v));
    return make_float2(__uint_as_float(lo), __uint_as_float(hi));
}

// ---------------- kernel A: xl, qp copy, weight packing -------------------
// blocks 0..127: xl (128 rows each); 128: Wm1b; 129: Wm2b; 130..145: W2q
__global__ __launch_bounds__(256) void k_xl(const float* __restrict__ x,
                                            const float* __restrict__ W,
                                            const float* __restrict__ bl,
                                            const float* __restrict__ qp,
                                            float* __restrict__ out,
                                            const float* __restrict__ Wm1,
                                            const float* __restrict__ Wm2,
                                            const float* __restrict__ W2,
                                            const float* __restrict__ filt){
    const int bid = blockIdx.x, tid = threadIdx.x;
    if(bid >= 128){
        const int tb = bid - 128;
        if(tb == 0){
            for(int i=tid;i<16384;i+=256){
                int d = i>>8, ii = i&255;
                d_Wm1b[(d>>2)*1024 + ii*4 + (d&3)] = Wm1[i];
            }
        } else if(tb == 1){
            for(int i=tid;i<16384;i+=256){
                int ii = i>>6, d = i&63;
                d_Wm2b[(ii>>2)*256 + d*4 + (ii&3)] = Wm2[i];
            }
        } else {
            int i0 = (tb-2)*4224;
            for(int i=i0+tid; i<i0+4224; i+=256){
                int t = i&3, ln = (i>>2)&31, c2 = (i>>7)&15, j = i>>11;
                int c = 2*c2 + (t&1);
                int d = ln + 32*(((t+1)>>1)&1);
                d_W2q[i] = (j<32) ? W2[(j<<11)+(c<<6)+d] : filt[(c<<6)+d];
            }
        }
        return;
    }
    __shared__ float sW[CC*CC];
    for(int i=tid;i<CC*CC;i+=256) sW[i]=W[i];
    __syncthreads();
    const int lane = tid&31;
    const int rbase = bid*128 + (tid>>5)*16;
    float xv[16];
    #pragma unroll
    for(int r=0;r<16;r++) xv[r] = x[(rbase+r)*CC + lane];
    #pragma unroll 4
    for(int r=0;r<16;r++){
        float acc = bl[lane];
        #pragma unroll
        for(int ci=0;ci<CC;ci++)
            acc = fmaf(__shfl_sync(0xffffffffu, xv[r], ci), sW[ci*CC+lane], acc);
        d_xl[(rbase+r)*CC+lane] = acc;
    }
    if(bid < 2){
        int i = bid*256 + tid;
        out[BB*QQ*DD + i] = qp[i];
    }
}

// ---------------- fused kernel ---------------------------------------------
// smem layout (floats). Total ~26660 floats = 106,640 B -> 2 blocks/SM.
#define OFF_G   0                 // g 205*36=7380 (later: epilogue partials, sh1)
#define OFF_X   7380              // 16384: sed+sfeat (low) | x gather buffers | sM
#define OFF_IND 23764             // 208 ints
#define OFF_Y   23972             // 512
#define OFF_EXT 24484             // extension: persistent select scratch
#define XE_D0   (OFF_EXT+0)       // 208
#define XE_D1   (OFF_EXT+208)
#define XE_EDK  (OFF_EXT+416)
#define XE_KD   (OFF_EXT+624)
#define XE_W1   (OFF_EXT+832)     // 1024
#define XE_B1   (OFF_EXT+1856)    // 32
#define XE_HIST (OFF_EXT+1888)    // 256 (uint)
#define XE_RA   (OFF_EXT+2144)    // 9
#define XE_RB   (OFF_EXT+2153)    // 9
#define XE_SC   (OFF_EXT+2162)    // 8 scalars
#define SMEM_FLOATS (OFF_EXT+2170)
#define SMEM_BYTES (SMEM_FLOATS*4)

__global__ __launch_bounds__(NT,2) void k_fused(
        const float* __restrict__ pos, const float* __restrict__ qpos,
        const float* __restrict__ rffB,
        const float* __restrict__ W1,  const float* __restrict__ b1,
        const float* __restrict__ qmw, const float* __restrict__ qmo,
        const float* __restrict__ bias,
        const float* __restrict__ bm1, const float* __restrict__ bm2,
        float* __restrict__ out)
{
    extern __shared__ float smem[];
    float* sg  = smem + OFF_G;
    float* px  = smem + OFF_X;
    int*   sind= (int*)(smem + OFF_IND);
    float* sy  = smem + OFF_Y;

    const int q = blockIdx.x, tid = threadIdx.x;
    const int warp = tid>>5, lane = tid&31;
    const float qx = qpos[q*2], qy = qpos[q*2+1];

    float* xbE = px + 8192;    // even-chunk gather buffer (also candidate list early)
    float* xbO = px;           // odd-chunk gather buffer (overlays sed/sfeat)

    // ======================= SELECT PHASE =======================
    {
        float* sed  = px;                    // 2048, dead after sedk gather
        float* sfeat= px;                    // 205*32=6560, written after sed dies
        int*   cand = (int*)xbE;             // candidate list (cap 2048), dead before gather
        float* sd0  = smem + XE_D0;
        float* sd1  = smem + XE_D1;
        float* sedk = smem + XE_EDK;
        float* skd  = smem + XE_KD;
        float* sW1  = smem + XE_W1;
        float* sb1  = smem + XE_B1;
        unsigned int* hist = (unsigned int*)(smem + XE_HIST);
        float* rbufA= smem + XE_RA;
        float* rbufB= smem + XE_RB;
        unsigned int* s_prefix = (unsigned int*)(smem + XE_SC);
        unsigned int* s_r      = (unsigned int*)(smem + XE_SC + 1);
        unsigned int* s_cnt    = (unsigned int*)(smem + XE_SC + 2);
        unsigned int* s_cand   = (unsigned int*)(smem + XE_SC + 3);
        float* s_min = smem + XE_SC + 4;
        float* s_max = smem + XE_SC + 5;
        float* s_sum = smem + XE_SC + 6;

        for(int i=tid;i<CC*CC;i+=NT) sW1[i]=W1[i];
        if(tid<CC) sb1[tid]=b1[tid];
        for(int i=tid;i<256;i+=NT) hist[i]=0u;
        if(tid==0){ *s_prefix=0u; *s_r=RANK; *s_cnt=0u; *s_cand=0u; }
        __syncthreads();

        // ---- edist + fused pass-0 histogram (warp-aggregated) ----
        for(int base=0; base<NN; base+=NT){
            int n = base + tid;
            bool inb = (n < NN);
            unsigned int k = 0xFFFFFFFFu;
            if(inb){
                float2 p = ((const float2*)pos)[n];
                float d0 = qx - p.x; d0 += 0.5f; d0 -= floorf(d0); d0 -= 0.5f;
                float d1 = qy - p.y; d1 += 0.5f; d1 -= floorf(d1); d1 -= 0.5f;
                float e = d0*d0 + d1*d1;
                sed[n] = e;
                k = __float_as_uint(e);
            }
            unsigned amask = __ballot_sync(0xffffffffu, inb);
            if(inb){
                unsigned bkt = (k>>24)&255u;
                unsigned peers = __match_any_sync(amask, bkt);
                if(lane == (int)(__ffs(peers)-1))
                    atomicAdd(&hist[bkt], __popc(peers));
            }
        }
        __syncthreads();
        if(warp == 0){
            const unsigned rr = *s_r;
            unsigned cnt[8]; unsigned s = 0;
            const int b0 = lane*8;
            #pragma unroll
            for(int t=0;t<8;t++){ cnt[t] = hist[b0+t]; s += cnt[t]; }
            unsigned excl = s;
            #pragma unroll
            for(int o=1;o<32;o<<=1){
                unsigned v = __shfl_up_sync(0xffffffffu, excl, o);
                if(lane >= o) excl += v;
            }
            excl -= s;
            bool sel = (excl <= rr) && (rr < excl + s);
            if(sel){
                unsigned rem = rr - excl;
                int t = 0;
                while(t < 7 && rem >= cnt[t]){ rem -= cnt[t]; t++; }
                *s_prefix = (unsigned)(b0+t) << 24;
                *s_r = rem;
            }
        }
        __syncthreads();

        // ---- single full scan: bkt<B0 -> sind directly; bkt==B0 -> candidates
        const unsigned B0 = (*s_prefix) >> 24;
        for(int n=tid;n<NN;n+=NT){
            unsigned bkt = __float_as_uint(sed[n]) >> 24;
            if(bkt < B0){ unsigned p = atomicAdd(s_cnt,1u); sind[p]=n; }
            else if(bkt == B0){ unsigned p = atomicAdd(s_cand,1u); cand[p]=n; }
        }
        __syncthreads();
        const int ncand = (int)*s_cand;

        // ---- passes 1-3 over candidates only ----
        for(int pass=1; pass<4; ++pass){
            const int shift = 24 - 8*pass;
            for(int i=tid;i<256;i+=NT) hist[i]=0u;
            __syncthreads();
            const unsigned int prefix = *s_prefix;
            const unsigned int hm = 0xFFFFFFFFu << (shift+8);
            for(int i=tid;i<ncand;i+=NT){
                unsigned int k = __float_as_uint(sed[cand[i]]);
                if((k & hm) == prefix) atomicAdd(&hist[(k>>shift)&255u], 1u);
            }
            __syncthreads();
            if(warp == 0){
                const unsigned rr = *s_r;
                unsigned cnt[8]; unsigned s = 0;
                const int b0 = lane*8;
                #pragma unroll
                for(int t=0;t<8;t++){ cnt[t] = hist[b0+t]; s += cnt[t]; }
                unsigned excl = s;
                #pragma unroll
                for(int o=1;o<32;o<<=1){
                    unsigned v = __shfl_up_sync(0xffffffffu, excl, o);
                    if(lane >= o) excl += v;
                }
                excl -= s;
                bool sel = (excl <= rr) && (rr < excl + s);
                if(sel){
                    unsigned rem = rr - excl;
                    int t = 0;
                    while(t < 7 && rem >= cnt[t]){ rem -= cnt[t]; t++; }
                    *s_prefix = prefix | ((unsigned)(b0+t) << shift);
                    *s_r = rem;
                }
            }
            __syncthreads();
        }
        const unsigned int T = *s_prefix;

        // ---- final selection among candidates ----
        for(int i=tid;i<ncand;i+=NT){
            int n = cand[i];
            unsigned int k = __float_as_uint(sed[n]);
            if(k < T){ unsigned int p = atomicAdd(s_cnt,1u); sind[p]=n; }
        }
        __syncthreads();
        for(int i=tid;i<ncand;i+=NT){
            int n = cand[i];
            unsigned int k = __float_as_uint(sed[n]);
            if(k == T){ unsigned int p = atomicAdd(s_cnt,1u); if(p<KK) sind[p]=n; }
        }
        __syncthreads();

        // gather dist/edist for selected set (sed dies after this)
        for(int k2=tid;k2<KK;k2+=NT){
            int n = sind[k2];
            float2 p = ((const float2*)pos)[n];
            float d0 = qx - p.x; d0 += 0.5f; d0 -= floorf(d0); d0 -= 0.5f;
            float d1 = qy - p.y; d1 += 0.5f; d1 -= floorf(d1); d1 -= 0.5f;
            sd0[k2]=d0; sd1[k2]=d1; sedk[k2]=sed[n];
        }
        __syncthreads();

        // ---- EARLY chunk-0 gather into xbE (candidates dead) ----
        for(int i=tid;i<32*64;i+=NT){
            int kk=i>>6, ch=i&63, b=ch>>3, c4=ch&7;
            int n = sind[kk];
            cp_async16(&xbE[kk*256 + ch*4], (const float4*)&d_xl[((b<<11)+n)*CC] + c4);
        }
        CP_COMMIT();

        float mn = 1e30f, mx = -1e30f;
        for(int k2=tid;k2<KK;k2+=NT){ mn=fminf(mn,sedk[k2]); mx=fmaxf(mx,sedk[k2]); }
        #pragma unroll
        for(int o=16;o>0;o>>=1){
            mn = fminf(mn, __shfl_down_sync(0xffffffffu,mn,o));
            mx = fmaxf(mx, __shfl_down_sync(0xffffffffu,mx,o));
        }
        if(lane==0){ rbufA[warp]=mn; rbufB[warp]=mx; }
        __syncthreads();
        if(tid==0){
            float a=rbufA[0], b=rbufB[0];
            for(int w=1;w<9;w++){ a=fminf(a,rbufA[w]); b=fmaxf(b,rbufB[w]); }
            *s_min=a; *s_max=b;
        }
        __syncthreads();

        const float inv = 1.0f/(*s_max - *s_min + 1e-8f);
        const float smin = *s_min;
        float lsum = 0.0f;
        for(int k2=tid;k2<KK;k2+=NT){
            float w = __expf(-(sedk[k2]-smin)*inv);
            skd[k2]=w; lsum+=w;
        }
        #pragma unroll
        for(int o=16;o>0;o>>=1) lsum += __shfl_down_sync(0xffffffffu,lsum,o);
        if(lane==0) rbufA[warp]=lsum;
        __syncthreads();
        if(tid==0){
            float s=0.f; for(int w=0;w<9;w++) s+=rbufA[w];
            *s_sum=s;
        }
        __syncthreads();
        const float invsum = 1.0f/(*s_sum);

        // RFF features into sfeat (= px[0..6560), sed dead)
        for(int i=tid;i<KK*16;i+=NT){
            int k2=i>>4, j=i&15;
            float pr = 6.28318530717958647692f*(sd0[k2]*rffB[j] + sd1[k2]*rffB[16+j]);
            float s,c; __sincosf(pr,&s,&c);
            sfeat[k2*32+j]=s; sfeat[k2*32+16+j]=c;
        }
        __syncthreads();

        // g-phase: k2-inner, W1 hoisted (iip fixed per thread: 288 % 16 == 0)
        {
            const int iip = (tid&15)*2;
            const int k2b = tid>>4;             // 0..17; k2 = k2b + 18*t
            u64t A[12];
            u64t binit = *(const u64t*)&sb1[iip];
            #pragma unroll
            for(int t=0;t<12;t++) A[t]=binit;
            #pragma unroll
            for(int f4=0; f4<8; ++f4){
                u64t w0 = *(const u64t*)&sW1[(4*f4+0)*CC+iip];
                u64t w1 = *(const u64t*)&sW1[(4*f4+1)*CC+iip];
                u64t w2 = *(const u64t*)&sW1[(4*f4+2)*CC+iip];
                u64t w3 = *(const u64t*)&sW1[(4*f4+3)*CC+iip];
                #pragma unroll
                for(int t=0;t<12;t++){
                    int k2 = k2b + 18*t;
                    if(k2 < KK){
                        float4 fv = *(const float4*)&sfeat[k2*32 + 4*f4];
                        ffma2(A[t], pack_dup(fv.x), w0);
                        ffma2(A[t], pack_dup(fv.y), w1);
                        ffma2(A[t], pack_dup(fv.z), w2);
                        ffma2(A[t], pack_dup(fv.w), w3);
                    }
                }
            }
            float2 qw = *(const float2*)&qmw[q*CC+iip];
            float2 qo = *(const float2*)&qmo[q*CC+iip];
            #pragma unroll
            for(int t=0;t<12;t++){
                int k2 = k2b + 18*t;
                if(k2 < KK){
                    float2 ac = unpack2(A[t]);
                    float h0 = ac.x*qw.x + qo.x;
                    float h1 = ac.y*qw.y + qo.y;
                    float kd = skd[k2]*invsum;
                    *(float2*)&sg[k2*JP + iip] = make_float2(gelu_f(h0)*kd, gelu_f(h1)*kd);
                }
            }
        }
        for(int k2=tid;k2<KK;k2+=NT){
            sg[k2*JP+32] = skd[k2]*invsum;
        }
        __syncthreads();
    }
    // ======================= M-GEMM PHASE (packed f32x2, low-wavefront tiling)
    const int jg = warp>>1, half = warp&1;

    u64t acc2[4][4];
    #pragma unroll
    for(int jj=0;jj<4;jj++)
        #pragma unroll
        for(int p=0;p<4;p++) acc2[jj][p]=0ull;

    const int NCH = (KK + 31)/32;  // 7
    for(int ci=0; ci<NCH; ++ci){
        const int k0 = ci*32;
        const int nk = (KK-k0 < 32) ? (KK-k0) : 32;
        if(ci+1 < NCH){
            const int k0n = k0+32;
            const int nkn = (KK-k0n < 32) ? (KK-k0n) : 32;
            float* dst = (ci&1) ? xbE : xbO;
            for(int i=tid;i<nkn*64;i+=NT){
                int kk=i>>6, ch=i&63, b=ch>>3, c4=ch&7;
                int n = sind[k0n+kk];
                cp_async16(&dst[kk*256 + ch*4], (const float4*)&d_xl[((b<<11)+n)*CC] + c4);
            }
            CP_COMMIT();
            CP_WAIT(1);
        } else {
            CP_WAIT(0);
        }
        __syncthreads();
        const float* xbase = (ci&1) ? xbO : xbE;
        const float4*     sx4 = (const float4*)xbase;
        const ulonglong2* sxu = (const ulonglong2*)xbase;
        if(warp < 8){
            #pragma unroll 2
            for(int kk=0; kk<nk; ++kk){
                const ulonglong2* gu = (const ulonglong2*)&sg[(k0+kk)*JP + jg*8];
                ulonglong2 g01 = gu[0];
                ulonglong2 g23 = gu[1];
                float4 xv = sx4[kk*64 + half*32 + lane];
                u64t x0 = pack_dup(xv.x);
                u64t x1 = pack_dup(xv.y);
                u64t x2 = pack_dup(xv.z);
                u64t x3 = pack_dup(xv.w);
                ffma2(acc2[0][0], g01.x, x0); ffma2(acc2[0][1], g01.x, x1);
                ffma2(acc2[0][2], g01.x, x2); ffma2(acc2[0][3], g01.x, x3);
                ffma2(acc2[1][0], g01.y, x0); ffma2(acc2[1][1], g01.y, x1);
                ffma2(acc2[1][2], g01.y, x2); ffma2(acc2[1][3], g01.y, x3);
                ffma2(acc2[2][0], g23.x, x0); ffma2(acc2[2][1], g23.x, x1);
                ffma2(acc2[2][2], g23.x, x2); ffma2(acc2[2][3], g23.x, x3);
                ffma2(acc2[3][0], g23.y, x0); ffma2(acc2[3][1], g23.y, x1);
                ffma2(acc2[3][2], g23.y, x2); ffma2(acc2[3][3], g23.y, x3);
            }
        } else {
            #pragma unroll 2
            for(int kk=0; kk<nk; ++kk){
                u64t kdd = pack_dup(sg[(k0+kk)*JP + 32]);
                ulonglong2 xa = sxu[kk*64 + lane];
                ulonglong2 xc = sxu[kk*64 + 32 + lane];
                ffma2(acc2[0][0], kdd, xa.x); ffma2(acc2[0][1], kdd, xa.y);
                ffma2(acc2[0][2], kdd, xc.x); ffma2(acc2[0][3], kdd, xc.y);
            }
        }
        __syncthreads();
    }

    // stage M (33 x 256) into smem (aliases gather buffers; all reads done)
    float* sM = px;
    if(warp < 8){
        const int c0 = half*128 + 4*lane;
        #pragma unroll
        for(int jp=0;jp<4;jp++){
            int j = jg*8 + 2*jp;
            float2 a0 = unpack2(acc2[jp][0]);
            float2 a1 = unpack2(acc2[jp][1]);
            float2 a2 = unpack2(acc2[jp][2]);
            float2 a3 = unpack2(acc2[jp][3]);
            *(float4*)&sM[j*256 + c0]     = make_float4(a0.x,a1.x,a2.x,a3.x);
            *(float4*)&sM[(j+1)*256 + c0] = make_float4(a0.y,a1.y,a2.y,a3.y);
        }
    } else {
        ulonglong2 v0; v0.x = acc2[0][0]; v0.y = acc2[0][1];
        ulonglong2 v1; v1.x = acc2[0][2]; v1.y = acc2[0][3];
        *(ulonglong2*)&sM[32*256 + 4*lane]       = v0;
        *(ulonglong2*)&sM[32*256 + 128 + 4*lane] = v1;
    }
    __syncthreads();

    // ======================= W2 EPILOGUE (unit-balanced, 2-deep prefetch) ==
    float* sp = sg;   // 9*512 partials, overlays dead g
    {
        const int u0 = (warp*528)/9;
        const int u1 = ((warp+1)*528)/9;
        const int nu = u1 - u0;
        u64t accA[8], accB[8];
        #pragma unroll
        for(int b=0;b<8;b++){ accA[b]=0ull; accB[b]=0ull; }
        const ulonglong2* wqp = (const ulonglong2*)d_W2q + lane;
        const u64t* m2b = (const u64t*)sM;
        ulonglong2 wv0 = wqp[(size_t)u0*32];
        ulonglong2 wv1 = (nu>1) ? wqp[(size_t)(u0+1)*32] : wv0;
        for(int t=0;t<nu;++t){
            const int u = u0+t;
            ulonglong2 wv2 = wv1;
            if(t+2 < nu) wv2 = wqp[(size_t)(u+2)*32];
            const int j = u>>4, c2 = u&15;
            const u64t* m2 = m2b + j*128;
            #pragma unroll
            for(int b=0;b<8;b++){
                u64t m = m2[b*16+c2];
                ffma2(accA[b], m, wv0.x);
                ffma2(accB[b], m, wv0.y);
            }
            wv0 = wv1; wv1 = wv2;
        }
        #pragma unroll
        for(int b=0;b<8;b++){
            float2 fa = unpack2(accA[b]);
            float2 fb = unpack2(accB[b]);
            sp[warp*512 + b*64 + lane]      = fa.x + fb.y;
            sp[warp*512 + b*64 + lane + 32] = fb.x + fa.y;
        }
    }
    __syncthreads();
    for(int o=tid; o<BB*DD; o+=NT){
        float s = 0.f;
        #pragma unroll
        for(int w=0;w<9;w++) s += sp[w*512+o];
        sy[o] = gelu_f(s + bias[o&63]);
    }
    __syncthreads();

    // ======================= MLP (packed weights, de-duplicated) ===========
    float* sh1 = sg;   // 2048 floats, overlays dead partials
    if(tid < 256){
        const int i = tid;
        const ulonglong2* wu = (const ulonglong2*)d_Wm1b;
        const ulonglong2* yu = (const ulonglong2*)sy;
        u64t A[8];
        #pragma unroll
        for(int b=0;b<8;b++) A[b]=0ull;
        #pragma unroll 4
        for(int d4=0; d4<16; ++d4){
            ulonglong2 w = wu[d4*256 + i];
            #pragma unroll
            for(int b=0;b<8;b++){
                ulonglong2 yv = yu[b*16 + d4];
                ffma2(A[b], yv.x, w.x);
                ffma2(A[b], yv.y, w.y);
            }
        }
        const float bi = bm1[i];
        #pragma unroll
        for(int b=0;b<8;b++){
            float2 f = unpack2(A[b]);
            sh1[b*256 + i] = gelu_f(f.x + f.y + bi);
        }
    }
    __syncthreads();

    if(tid < 256){
        const int d = tid&63;
        const int b0 = (tid>>6)*2, b1 = b0+1;
        const ulonglong2* wu = (const ulonglong2*)d_Wm2b;
        const ulonglong2* hu = (const ulonglong2*)sh1;
        u64t A0=0ull, A1=0ull;
        #pragma unroll 8
        for(int i4=0; i4<64; ++i4){
            ulonglong2 w  = wu[i4*64 + d];
            ulonglong2 h0 = hu[b0*64 + i4];
            ulonglong2 h1v= hu[b1*64 + i4];
            ffma2(A0, h0.x, w.x);  ffma2(A0, h0.y, w.y);
            ffma2(A1, h1v.x, w.x); ffma2(A1, h1v.y, w.y);
        }
        float2 f0 = unpack2(A0), f1 = unpack2(A1);
        const float bd = bm2[d];
        out[(b0*QQ + q)*DD + d] = f0.x + f0.y + bd + sy[b0*64 + d];
        out[(b1*QQ + q)*DD + d] = f1.x + f1.y + bd + sy[b1*64 + d];
    }
}

// ---------------- launch --------------------------------------------------
extern "C" void kernel_launch(void* const* d_in, const int* in_sizes, int n_in,
                              void* d_out, int out_size){
    (void)in_sizes; (void)n_in; (void)out_size;
    const float* x     = (const float*)d_in[0];
    const float* pos   = (const float*)d_in[1];
    const float* qpos  = (const float*)d_in[2];
    const float* qmw   = (const float*)d_in[3];
    const float* qmo   = (const float*)d_in[4];
    const float* W_lin = (const float*)d_in[5];
    const float* b_lin = (const float*)d_in[6];
    const float* rffB  = (const float*)d_in[7];
    const float* W1    = (const float*)d_in[8];
    const float* b1    = (const float*)d_in[9];
    const float* W2    = (const float*)d_in[10];
    const float* filt  = (const float*)d_in[11];
    const float* bias  = (const float*)d_in[12];
    const float* Wm1   = (const float*)d_in[13];
    const float* bm1   = (const float*)d_in[14];
    const float* Wm2   = (const float*)d_in[15];
    const float* bm2   = (const float*)d_in[16];
    float* out = (float*)d_out;

    cudaFuncSetAttribute(k_fused, cudaFuncAttributeMaxDynamicSharedMemorySize, SMEM_BYTES);

    k_xl   <<<128+2+16, 256>>>(x, W_lin, b_lin, qpos, out, Wm1, Wm2, W2, filt);
    k_fused<<<QQ, NT, SMEM_BYTES>>>(pos, qpos, rffB, W1, b1, qmw, qmo,
                                    bias, bm1, bm2, out);
}